// round 16
// baseline (speedup 1.0000x reference)
#include <cuda_runtime.h>
#include <cuda_fp16.h>

#define NN   50000
#define EE   800000
#define INC  32
#define HIDC 64
#define MAXDEG 96

// -------------------- device scratch (no allocation allowed) ----------------
// Invariant: g_cnt is ZERO at entry of every kernel_launch call
// (zeroed at module load; restored by k_agg2 each call).
__device__ __align__(16) int    g_cnt[NN];            // degree + fill cursor
__device__ __align__(16) int    g_csrp[NN * MAXDEG];  // padded CSR: src by dst
__device__ __align__(16) __half g_xh[NN * INC];       // x in fp16
__device__ __align__(16) __half g_agg1h[NN * INC];    // normalized mean of x (fp16)
__device__ __align__(16) __half g_agg2h[NN * HIDC];   // normalized mean of h (fp16)
__device__ __align__(16) __half g_h[NN * HIDC];       // layer-1 output (fp16)

// -------------------- packed math helpers -----------------------------------
__device__ __forceinline__ unsigned long long pack2(float lo, float hi) {
    unsigned long long r;
    asm("mov.b64 %0, {%1, %2};" : "=l"(r) : "f"(lo), "f"(hi));
    return r;
}
__device__ __forceinline__ void unpack2(float& lo, float& hi, unsigned long long v) {
    asm("mov.b64 {%0, %1}, %2;" : "=f"(lo), "=f"(hi) : "l"(v));
}
#define ADD2(d, a) asm("add.rn.f32x2 %0, %0, %1;" : "+l"(d) : "l"(a))

// -------------------- tensor-core helpers ------------------------------------
__device__ __forceinline__ void ldsm_x4(unsigned* r, unsigned addr) {
    asm volatile("ldmatrix.sync.aligned.m8n8.x4.shared.b16 {%0,%1,%2,%3}, [%4];"
                 : "=r"(r[0]), "=r"(r[1]), "=r"(r[2]), "=r"(r[3]) : "r"(addr));
}
__device__ __forceinline__ void ldsm_x2t(unsigned& r0, unsigned& r1, unsigned addr) {
    asm volatile("ldmatrix.sync.aligned.m8n8.x2.trans.shared.b16 {%0,%1}, [%2];"
                 : "=r"(r0), "=r"(r1) : "r"(addr));
}
__device__ __forceinline__ void mma16816(float* d, const unsigned* a,
                                         unsigned b0, unsigned b1) {
    asm volatile("mma.sync.aligned.m16n8k16.row.col.f32.f16.f16.f32 "
                 "{%0,%1,%2,%3}, {%4,%5,%6,%7}, {%8,%9}, {%0,%1,%2,%3};"
                 : "+f"(d[0]), "+f"(d[1]), "+f"(d[2]), "+f"(d[3])
                 : "r"(a[0]), "r"(a[1]), "r"(a[2]), "r"(a[3]), "r"(b0), "r"(b1));
}

// ============================================================================
// Fill + x->fp16 convert in one grid.
// ============================================================================
#define FILL_T   (EE / 4)                    // 200000
#define XCVT_T   (NN * INC / 8)              // 200000

__global__ __launch_bounds__(256)
void k_fill(const int* __restrict__ src, const int* __restrict__ dst,
            const float* __restrict__ x) {
    int q = blockIdx.x * blockDim.x + threadIdx.x;
    if (q < FILL_T) {
        int4 s4 = __ldg((const int4*)src + q);
        int4 d4 = __ldg((const int4*)dst + q);
        int sl0 = atomicAdd(&g_cnt[d4.x], 1);
        int sl1 = atomicAdd(&g_cnt[d4.y], 1);
        int sl2 = atomicAdd(&g_cnt[d4.z], 1);
        int sl3 = atomicAdd(&g_cnt[d4.w], 1);
        if (sl0 < MAXDEG) g_csrp[d4.x * MAXDEG + sl0] = s4.x;
        if (sl1 < MAXDEG) g_csrp[d4.y * MAXDEG + sl1] = s4.y;
        if (sl2 < MAXDEG) g_csrp[d4.z * MAXDEG + sl2] = s4.z;
        if (sl3 < MAXDEG) g_csrp[d4.w * MAXDEG + sl3] = s4.w;
    } else if (q < FILL_T + XCVT_T) {
        int i = q - FILL_T;                  // 8-float chunk id
        float4 a = __ldg((const float4*)x + 2 * i);
        float4 b = __ldg((const float4*)x + 2 * i + 1);
        __half2 h0 = __floats2half2_rn(a.x, a.y);
        __half2 h1 = __floats2half2_rn(a.z, a.w);
        __half2 h2 = __floats2half2_rn(b.x, b.y);
        __half2 h3 = __floats2half2_rn(b.z, b.w);
        uint4 u;
        u.x = *(unsigned int*)&h0;
        u.y = *(unsigned int*)&h1;
        u.z = *(unsigned int*)&h2;
        u.w = *(unsigned int*)&h3;
        ((uint4*)g_xh)[i] = u;
    }
}

// ============================================================================
// Agg 1: 8 nodes per warp; 4 lanes x uint4 (8 fp16) cover the 32 channels.
// (identical to measured R15)
// ============================================================================
__global__ __launch_bounds__(256)
void k_agg1() {
    int gt   = blockIdx.x * blockDim.x + threadIdx.x;
    int wid  = gt >> 5;
    int lane = gt & 31;
    int sub  = lane >> 2;        // node within warp (0..7)
    int c4   = lane & 3;         // uint4 group (0..3)
    int n = wid * 8 + sub;
    if (n >= NN) return;

    int deg  = g_cnt[n];
    int degc = deg < MAXDEG ? deg : MAXDEG;
    const int*   row = &g_csrp[n * MAXDEG];
    const uint4* xp  = (const uint4*)g_xh;   // 4 uint4 per row

    unsigned long long ac[4];
#pragma unroll
    for (int i = 0; i < 4; i++) ac[i] = 0ull;

    int j = 0;
    for (; j + 7 < degc; j += 8) {
        int4 sA = __ldg((const int4*)(row + j));
        int4 sB = __ldg((const int4*)(row + j + 4));
        uint4 u0 = __ldg(xp + (sA.x * 4 + c4));
        uint4 u1 = __ldg(xp + (sA.y * 4 + c4));
        uint4 u2 = __ldg(xp + (sA.z * 4 + c4));
        uint4 u3 = __ldg(xp + (sA.w * 4 + c4));
        uint4 u4 = __ldg(xp + (sB.x * 4 + c4));
        uint4 u5 = __ldg(xp + (sB.y * 4 + c4));
        uint4 u6 = __ldg(xp + (sB.z * 4 + c4));
        uint4 u7 = __ldg(xp + (sB.w * 4 + c4));
#pragma unroll
        for (int q = 0; q < 8; q++) {
            uint4 u = (q == 0) ? u0 : (q == 1) ? u1 : (q == 2) ? u2 :
                      (q == 3) ? u3 : (q == 4) ? u4 : (q == 5) ? u5 :
                      (q == 6) ? u6 : u7;
            float2 f0 = __half22float2(*(__half2*)&u.x);
            float2 f1 = __half22float2(*(__half2*)&u.y);
            float2 f2 = __half22float2(*(__half2*)&u.z);
            float2 f3 = __half22float2(*(__half2*)&u.w);
            ADD2(ac[0], pack2(f0.x, f0.y));
            ADD2(ac[1], pack2(f1.x, f1.y));
            ADD2(ac[2], pack2(f2.x, f2.y));
            ADD2(ac[3], pack2(f3.x, f3.y));
        }
    }
    for (; j < degc; j++) {
        uint4 u = __ldg(xp + (__ldg(row + j) * 4 + c4));
        float2 f0 = __half22float2(*(__half2*)&u.x);
        float2 f1 = __half22float2(*(__half2*)&u.y);
        float2 f2 = __half22float2(*(__half2*)&u.z);
        float2 f3 = __half22float2(*(__half2*)&u.w);
        ADD2(ac[0], pack2(f0.x, f0.y));
        ADD2(ac[1], pack2(f1.x, f1.y));
        ADD2(ac[2], pack2(f2.x, f2.y));
        ADD2(ac[3], pack2(f3.x, f3.y));
    }
    float dinv = 1.0f / fmaxf((float)deg, 1.0f);
    float lo, hi;
    uint4 pkt;
    unpack2(lo, hi, ac[0]);
    __half2 h0 = __floats2half2_rn(lo * dinv, hi * dinv);
    pkt.x = *(unsigned int*)&h0;
    unpack2(lo, hi, ac[1]);
    __half2 h1 = __floats2half2_rn(lo * dinv, hi * dinv);
    pkt.y = *(unsigned int*)&h1;
    unpack2(lo, hi, ac[2]);
    __half2 h2 = __floats2half2_rn(lo * dinv, hi * dinv);
    pkt.z = *(unsigned int*)&h2;
    unpack2(lo, hi, ac[3]);
    __half2 h3 = __floats2half2_rn(lo * dinv, hi * dinv);
    pkt.w = *(unsigned int*)&h3;
    ((uint4*)g_agg1h)[n * 4 + c4] = pkt;
}

// ============================================================================
// Agg 2: 2 warps per node, scalar FADD accumulation.
// Block = 8 warps = 4 warp-pairs; each pair handles 4 nodes (sub = lane>>3).
// Warp split s in {0,1} processes int4-quads q = s, s+2, s+4, ... of the CSR
// row; tail (<4) goes to the warp whose turn it is. Partial sums merged via
// smem. fp16 output; restores g_cnt[n] = 0.
// ============================================================================
__global__ __launch_bounds__(256)
void k_agg2() {
    __shared__ float red[16][HIDC];          // 16 nodes x 64 ch = 16 KB
    int t = threadIdx.x;
    int w = t >> 5, lane = t & 31;
    int pair  = w >> 1;          // 0..3
    int split = w & 1;           // 0 or 1
    int sub   = lane >> 3;       // node within pair-group (0..3)
    int c8    = lane & 7;        // 8-halves group (0..7)
    int nl = pair * 4 + sub;     // local node id (0..15)
    int n  = blockIdx.x * 16 + nl;
    bool valid = n < NN;

    float acc[8];
#pragma unroll
    for (int i = 0; i < 8; i++) acc[i] = 0.f;

    int deg = 0;
    if (valid) {
        deg = g_cnt[n];
        int degc = deg < MAXDEG ? deg : MAXDEG;
        const int*   row = &g_csrp[n * MAXDEG];
        const uint4* hp  = (const uint4*)g_h;
        int nq = degc >> 2;

        // Two quads per iteration for this warp (8 gathers in flight)
        int q = split;
        for (; q + 2 < nq; q += 4) {
            int4 sA = __ldg((const int4*)(row + q * 4));
            int4 sB = __ldg((const int4*)(row + (q + 2) * 4));
            uint4 u0 = __ldg(hp + (sA.x * 8 + c8));
            uint4 u1 = __ldg(hp + (sA.y * 8 + c8));
            uint4 u2 = __ldg(hp + (sA.z * 8 + c8));
            uint4 u3 = __ldg(hp + (sA.w * 8 + c8));
            uint4 u4 = __ldg(hp + (sB.x * 8 + c8));
            uint4 u5 = __ldg(hp + (sB.y * 8 + c8));
            uint4 u6 = __ldg(hp + (sB.z * 8 + c8));
            uint4 u7 = __ldg(hp + (sB.w * 8 + c8));
#pragma unroll
            for (int qq = 0; qq < 8; qq++) {
                uint4 u = (qq == 0) ? u0 : (qq == 1) ? u1 : (qq == 2) ? u2 :
                          (qq == 3) ? u3 : (qq == 4) ? u4 : (qq == 5) ? u5 :
                          (qq == 6) ? u6 : u7;
                float2 f0 = __half22float2(*(__half2*)&u.x);
                float2 f1 = __half22float2(*(__half2*)&u.y);
                float2 f2 = __half22float2(*(__half2*)&u.z);
                float2 f3 = __half22float2(*(__half2*)&u.w);
                acc[0] += f0.x; acc[1] += f0.y;
                acc[2] += f1.x; acc[3] += f1.y;
                acc[4] += f2.x; acc[5] += f2.y;
                acc[6] += f3.x; acc[7] += f3.y;
            }
        }
        for (; q < nq; q += 2) {
            int4 s = __ldg((const int4*)(row + q * 4));
            uint4 u0 = __ldg(hp + (s.x * 8 + c8));
            uint4 u1 = __ldg(hp + (s.y * 8 + c8));
            uint4 u2 = __ldg(hp + (s.z * 8 + c8));
            uint4 u3 = __ldg(hp + (s.w * 8 + c8));
#pragma unroll
            for (int qq = 0; qq < 4; qq++) {
                uint4 u = (qq == 0) ? u0 : (qq == 1) ? u1 : (qq == 2) ? u2 : u3;
                float2 f0 = __half22float2(*(__half2*)&u.x);
                float2 f1 = __half22float2(*(__half2*)&u.y);
                float2 f2 = __half22float2(*(__half2*)&u.z);
                float2 f3 = __half22float2(*(__half2*)&u.w);
                acc[0] += f0.x; acc[1] += f0.y;
                acc[2] += f1.x; acc[3] += f1.y;
                acc[4] += f2.x; acc[5] += f2.y;
                acc[6] += f3.x; acc[7] += f3.y;
            }
        }
        // Tail: elements [nq*4, degc) handled by the warp whose turn it is.
        if ((nq & 1) == split) {
            for (int j = nq * 4; j < degc; j++) {
                uint4 u = __ldg(hp + (__ldg(row + j) * 8 + c8));
                float2 f0 = __half22float2(*(__half2*)&u.x);
                float2 f1 = __half22float2(*(__half2*)&u.y);
                float2 f2 = __half22float2(*(__half2*)&u.z);
                float2 f3 = __half22float2(*(__half2*)&u.w);
                acc[0] += f0.x; acc[1] += f0.y;
                acc[2] += f1.x; acc[3] += f1.y;
                acc[4] += f2.x; acc[5] += f2.y;
                acc[6] += f3.x; acc[7] += f3.y;
            }
        }
    }

    // Merge partials: split=1 stores, split=0 adds + finalizes.
    if (split == 1) {
        float* rp = &red[nl][c8 * 8];
        *(float4*)(rp + 0) = make_float4(acc[0], acc[1], acc[2], acc[3]);
        *(float4*)(rp + 4) = make_float4(acc[4], acc[5], acc[6], acc[7]);
    }
    __syncthreads();
    if (split == 0 && valid) {
        const float* rp = &red[nl][c8 * 8];
        float4 r0 = *(const float4*)(rp + 0);
        float4 r1 = *(const float4*)(rp + 4);
        acc[0] += r0.x; acc[1] += r0.y; acc[2] += r0.z; acc[3] += r0.w;
        acc[4] += r1.x; acc[5] += r1.y; acc[6] += r1.z; acc[7] += r1.w;
        float dinv = 1.0f / fmaxf((float)deg, 1.0f);
        __half2 p0 = __floats2half2_rn(acc[0]*dinv, acc[1]*dinv);
        __half2 p1 = __floats2half2_rn(acc[2]*dinv, acc[3]*dinv);
        __half2 p2 = __floats2half2_rn(acc[4]*dinv, acc[5]*dinv);
        __half2 p3 = __floats2half2_rn(acc[6]*dinv, acc[7]*dinv);
        uint4 pkt;
        pkt.x = *(unsigned int*)&p0;
        pkt.y = *(unsigned int*)&p1;
        pkt.z = *(unsigned int*)&p2;
        pkt.w = *(unsigned int*)&p3;
        ((uint4*)g_agg2h)[n * 8 + c8] = pkt;
        if (c8 == 0) g_cnt[n] = 0;   // restore invariant
    }
}

// ============================================================================
// Layer 1 via tensor cores: D[128x64] = [agg1h | xh] @ [W1l;W1r]
// (identical to measured R15)
// ============================================================================
#define L1_KH    72
#define L1_NH    72
#define L1_SA    0                            // 128*72*2 = 18432
#define L1_SB    18432                        // 64*72*2  = 9216
#define L1_ALPHA (18432 + 9216)               // 27648
#define L1_BETA  (L1_ALPHA + 256)
#define L1_SMEM  (L1_BETA + 256)              // 28160

__global__ __launch_bounds__(256)
void k_layer1(const float* __restrict__ W1l, const float* __restrict__ b1l,
              const float* __restrict__ W1r,
              const float* __restrict__ g1, const float* __restrict__ bb1,
              const float* __restrict__ m1, const float* __restrict__ v1) {
    extern __shared__ char smem_raw[];
    __half* SA = (__half*)(smem_raw + L1_SA);
    __half* SB = (__half*)(smem_raw + L1_SB);
    float* SAL = (float*)(smem_raw + L1_ALPHA);
    float* SBE = (float*)(smem_raw + L1_BETA);

    int t = threadIdx.x;
    int nb = blockIdx.x * 128;
    int lane = t & 31, w = t >> 5;

#pragma unroll
    for (int it = 0; it < 4; it++) {
        int f = t + 256 * it;            // uint4 id [0,1024): m = f>>3, g = f&7
        int m = f >> 3, g = f & 7;
        int n = nb + m; int nc = n < NN ? n : NN - 1;
        uint4 u = (g < 4) ? __ldg((const uint4*)g_agg1h + (nc * 4 + g))
                          : __ldg((const uint4*)g_xh + (nc * 4 + (g - 4)));
        *(uint4*)&SA[m * L1_KH + g * 8] = u;
    }
#pragma unroll
    for (int it = 0; it < 4; it++) {
        int f4 = t + 256 * it;           // float4 id [0,1024)
        int k = f4 >> 4, j = f4 & 15;
        float4 wv = (f4 < 512) ? __ldg((const float4*)W1l + f4)
                               : __ldg((const float4*)W1r + (f4 - 512));
        __half2 h01 = __floats2half2_rn(wv.x, wv.y);
        __half2 h23 = __floats2half2_rn(wv.z, wv.w);
        uint2 p;
        p.x = *(unsigned int*)&h01;
        p.y = *(unsigned int*)&h23;
        *(uint2*)&SB[k * L1_NH + j * 4] = p;
    }
    if (t < HIDC) {
        float a = g1[t] * rsqrtf(v1[t] + 1e-5f);
        SAL[t] = a;
        SBE[t] = (b1l[t] - m1[t]) * a + bb1[t];
    }
    __syncthreads();

    int m0 = w * 16;
    float d[8][4];
#pragma unroll
    for (int j = 0; j < 8; j++)
#pragma unroll
        for (int i = 0; i < 4; i++) d[j][i] = 0.f;

    int arow = m0 + (lane & 15);
    int akk  = (lane >> 4) * 8;
    int brow = lane & 15;

#pragma unroll
    for (int s = 0; s < 4; s++) {
        unsigned afr[4];
        unsigned aaddr = (unsigned)__cvta_generic_to_shared(
            &SA[arow * L1_KH + s * 16 + akk]);
        ldsm_x4(afr, aaddr);
#pragma unroll
        for (int j = 0; j < 8; j++) {
            unsigned b0, b1;
            unsigned baddr = (unsigned)__cvta_generic_to_shared(
                &SB[(s * 16 + brow) * L1_NH + j * 8]);
            ldsm_x2t(b0, b1, baddr);
            mma16816(d[j], afr, b0, b1);
        }
    }

    int r0 = lane >> 2;
    int cbase = 2 * (lane & 3);
    int n1 = nb + m0 + r0;
    int n2 = n1 + 8;
#pragma unroll
    for (int j = 0; j < 8; j++) {
        int c = 8 * j + cbase;
        float A0 = SAL[c],   B0 = SBE[c];
        float A1 = SAL[c+1], B1 = SBE[c+1];
        if (n1 < NN) {
            __half2 hv = __floats2half2_rn(
                fmaxf(d[j][0] * A0 + B0, 0.f),
                fmaxf(d[j][1] * A1 + B1, 0.f));
            *(__half2*)&g_h[(long long)n1 * HIDC + c] = hv;
        }
        if (n2 < NN) {
            __half2 hv = __floats2half2_rn(
                fmaxf(d[j][2] * A0 + B0, 0.f),
                fmaxf(d[j][3] * A1 + B1, 0.f));
            *(__half2*)&g_h[(long long)n2 * HIDC + c] = hv;
        }
    }
}

// ============================================================================
// Layer 2 + head via tensor cores (identical to measured R13/R14/R15)
// ============================================================================
#define L2_KH    136                          // SA row stride (halves)
#define L2_NH    72                           // SB row stride (halves)
#define L2_SA    0                            // 128*136*2 = 34816
#define L2_SB    34816                        // 128*72*2  = 18432
#define L2_ALPHA (34816 + 18432)              // 53248
#define L2_BETA  (L2_ALPHA + 256)
#define L2_SWO   (L2_BETA + 256)
#define L2_SMEM  (L2_SWO + 256)               // 54016

__global__ __launch_bounds__(256)
void k_layer2(const float* __restrict__ W2l, const float* __restrict__ b2l,
              const float* __restrict__ W2r,
              const float* __restrict__ g2, const float* __restrict__ bb2,
              const float* __restrict__ m2, const float* __restrict__ v2,
              const float* __restrict__ Wlin, const float* __restrict__ blin,
              float* __restrict__ out) {
    extern __shared__ char smem_raw[];
    __half* SA = (__half*)(smem_raw + L2_SA);
    __half* SB = (__half*)(smem_raw + L2_SB);
    float* SAL = (float*)(smem_raw + L2_ALPHA);
    float* SBE = (float*)(smem_raw + L2_BETA);
    float* SWO = (float*)(smem_raw + L2_SWO);

    int t = threadIdx.x;
    int nb = blockIdx.x * 128;
    int lane = t & 31, w = t >> 5;

#pragma unroll
    for (int it = 0; it < 8; it++) {
        int f = t + 256 * it;            // uint4 id [0,2048)
        int m = f >> 4, g = f & 15;
        int n = nb + m; int nc = n < NN ? n : NN - 1;
        uint4 u = (g < 8) ? __ldg((const uint4*)g_agg2h + (nc * 8 + g))
                          : __ldg((const uint4*)g_h + (nc * 8 + (g - 8)));
        *(uint4*)&SA[m * L2_KH + g * 8] = u;
    }
#pragma unroll
    for (int it = 0; it < 8; it++) {
        int f4 = t + 256 * it;           // float4 id [0,2048)
        int k = f4 >> 4, j = f4 & 15;
        float4 wv = (f4 < 1024) ? __ldg((const float4*)W2l + f4)
                                : __ldg((const float4*)W2r + (f4 - 1024));
        __half2 h01 = __floats2half2_rn(wv.x, wv.y);
        __half2 h23 = __floats2half2_rn(wv.z, wv.w);
        uint2 p;
        p.x = *(unsigned int*)&h01;
        p.y = *(unsigned int*)&h23;
        *(uint2*)&SB[k * L2_NH + j * 4] = p;
    }
    if (t < HIDC) {
        float a = g2[t] * rsqrtf(v2[t] + 1e-5f);
        SAL[t] = a;
        SBE[t] = (b2l[t] - m2[t]) * a + bb2[t];
        SWO[t] = Wlin[t];
    }
    __syncthreads();

    int m0 = w * 16;
    float d[8][4];
#pragma unroll
    for (int j = 0; j < 8; j++)
#pragma unroll
        for (int i = 0; i < 4; i++) d[j][i] = 0.f;

    int arow = m0 + (lane & 15);
    int akk  = (lane >> 4) * 8;
    int brow = lane & 15;

#pragma unroll
    for (int s = 0; s < 8; s++) {
        unsigned afr[4];
        unsigned aaddr = (unsigned)__cvta_generic_to_shared(
            &SA[arow * L2_KH + s * 16 + akk]);
        ldsm_x4(afr, aaddr);
#pragma unroll
        for (int j = 0; j < 8; j++) {
            unsigned b0, b1;
            unsigned baddr = (unsigned)__cvta_generic_to_shared(
                &SB[(s * 16 + brow) * L2_NH + j * 8]);
            ldsm_x2t(b0, b1, baddr);
            mma16816(d[j], afr, b0, b1);
        }
    }

    int r0 = lane >> 2;
    int cbase = 2 * (lane & 3);
    float p0 = 0.f, p1 = 0.f;
#pragma unroll
    for (int j = 0; j < 8; j++) {
        int c = 8 * j + cbase;
        float A0 = SAL[c],   B0 = SBE[c],   W0 = SWO[c];
        float A1 = SAL[c+1], B1 = SBE[c+1], W1 = SWO[c+1];
        p0 += fmaxf(d[j][0] * A0 + B0, 0.f) * W0
            + fmaxf(d[j][1] * A1 + B1, 0.f) * W1;
        p1 += fmaxf(d[j][2] * A0 + B0, 0.f) * W0
            + fmaxf(d[j][3] * A1 + B1, 0.f) * W1;
    }
    p0 += __shfl_xor_sync(0xFFFFFFFFu, p0, 1);
    p0 += __shfl_xor_sync(0xFFFFFFFFu, p0, 2);
    p1 += __shfl_xor_sync(0xFFFFFFFFu, p1, 1);
    p1 += __shfl_xor_sync(0xFFFFFFFFu, p1, 2);
    if ((lane & 3) == 0) {
        float bb = __ldg(&blin[0]);
        int n1 = nb + m0 + r0;
        int n2 = n1 + 8;
        if (n1 < NN) out[n1] = p0 + bb;
        if (n2 < NN) out[n2] = p1 + bb;
    }
}

// ============================================================================
// Launch — 5 kernels
// ============================================================================
extern "C" void kernel_launch(void* const* d_in, const int* in_sizes, int n_in,
                              void* d_out, int out_size) {
    const float* x   = (const float*)d_in[0];
    const int*   ei  = (const int*)d_in[1];   // int32 (jax x64 disabled)
    const int*   src = ei;
    const int*   dst = ei + EE;
    const float* W1l  = (const float*)d_in[2];
    const float* b1l  = (const float*)d_in[3];
    const float* W1r  = (const float*)d_in[4];
    const float* bn1g = (const float*)d_in[5];
    const float* bn1b = (const float*)d_in[6];
    const float* bn1m = (const float*)d_in[7];
    const float* bn1v = (const float*)d_in[8];
    const float* W2l  = (const float*)d_in[9];
    const float* b2l  = (const float*)d_in[10];
    const float* W2r  = (const float*)d_in[11];
    const float* bn2g = (const float*)d_in[12];
    const float* bn2b = (const float*)d_in[13];
    const float* bn2m = (const float*)d_in[14];
    const float* bn2v = (const float*)d_in[15];
    const float* Wlin = (const float*)d_in[16];
    const float* blin = (const float*)d_in[17];
    float* out = (float*)d_out;

    cudaFuncSetAttribute(k_layer1, cudaFuncAttributeMaxDynamicSharedMemorySize, L1_SMEM);
    cudaFuncSetAttribute(k_layer2, cudaFuncAttributeMaxDynamicSharedMemorySize, L2_SMEM);

    int nblk  = (NN + 127) / 128;              // 391
    int fblk  = (FILL_T + XCVT_T + 255) / 256; // 1563
    int a1blk = (NN * 4 + 255) / 256;          // 782   (8 nodes/warp)
    int a2blk = (NN + 15) / 16;                // 3125  (16 nodes/block, 2 warps/node)

    k_fill<<<fblk, 256>>>(src, dst, x);
    k_agg1<<<a1blk, 256>>>();
    k_layer1<<<nblk, 256, L1_SMEM>>>(W1l, b1l, W1r, bn1g, bn1b, bn1m, bn1v);
    k_agg2<<<a2blk, 256>>>();
    k_layer2<<<nblk, 256, L2_SMEM>>>(W2l, b2l, W2r, bn2g, bn2b, bn2m, bn2v,
                                     Wlin, blin, out);
}

// round 17
// speedup vs baseline: 1.0510x; 1.0510x over previous
#include <cuda_runtime.h>
#include <cuda_fp16.h>

#define NN   50000
#define EE   800000
#define INC  32
#define HIDC 64
#define MAXDEG 96

// -------------------- device scratch (no allocation allowed) ----------------
// Invariant: g_cnt is ZERO at entry of every kernel_launch call
// (zeroed at module load; restored by k_agg2 each call).
__device__ __align__(16) int    g_cnt[NN];            // degree + fill cursor
__device__ __align__(16) int    g_csrp[NN * MAXDEG];  // padded CSR: src by dst
__device__ __align__(16) __half g_xh[NN * INC];       // x in fp16
__device__ __align__(16) __half g_agg1h[NN * INC];    // normalized mean of x (fp16)
__device__ __align__(16) __half g_agg2h[NN * HIDC];   // normalized mean of h (fp16)
__device__ __align__(16) __half g_h[NN * HIDC];       // layer-1 output (fp16)

// -------------------- packed math helpers -----------------------------------
__device__ __forceinline__ unsigned long long pack2(float lo, float hi) {
    unsigned long long r;
    asm("mov.b64 %0, {%1, %2};" : "=l"(r) : "f"(lo), "f"(hi));
    return r;
}
__device__ __forceinline__ void unpack2(float& lo, float& hi, unsigned long long v) {
    asm("mov.b64 {%0, %1}, %2;" : "=f"(lo), "=f"(hi) : "l"(v));
}
#define ADD2(d, a) asm("add.rn.f32x2 %0, %0, %1;" : "+l"(d) : "l"(a))

// -------------------- tensor-core helpers ------------------------------------
__device__ __forceinline__ void ldsm_x4(unsigned* r, unsigned addr) {
    asm volatile("ldmatrix.sync.aligned.m8n8.x4.shared.b16 {%0,%1,%2,%3}, [%4];"
                 : "=r"(r[0]), "=r"(r[1]), "=r"(r[2]), "=r"(r[3]) : "r"(addr));
}
__device__ __forceinline__ void ldsm_x2t(unsigned& r0, unsigned& r1, unsigned addr) {
    asm volatile("ldmatrix.sync.aligned.m8n8.x2.trans.shared.b16 {%0,%1}, [%2];"
                 : "=r"(r0), "=r"(r1) : "r"(addr));
}
__device__ __forceinline__ void mma16816(float* d, const unsigned* a,
                                         unsigned b0, unsigned b1) {
    asm volatile("mma.sync.aligned.m16n8k16.row.col.f32.f16.f16.f32 "
                 "{%0,%1,%2,%3}, {%4,%5,%6,%7}, {%8,%9}, {%0,%1,%2,%3};"
                 : "+f"(d[0]), "+f"(d[1]), "+f"(d[2]), "+f"(d[3])
                 : "r"(a[0]), "r"(a[1]), "r"(a[2]), "r"(a[3]), "r"(b0), "r"(b1));
}

// ============================================================================
// Fill + x->fp16 convert in one grid.
// ============================================================================
#define FILL_T   (EE / 4)                    // 200000
#define XCVT_T   (NN * INC / 8)              // 200000

__global__ __launch_bounds__(256)
void k_fill(const int* __restrict__ src, const int* __restrict__ dst,
            const float* __restrict__ x) {
    int q = blockIdx.x * blockDim.x + threadIdx.x;
    if (q < FILL_T) {
        int4 s4 = __ldg((const int4*)src + q);
        int4 d4 = __ldg((const int4*)dst + q);
        int sl0 = atomicAdd(&g_cnt[d4.x], 1);
        int sl1 = atomicAdd(&g_cnt[d4.y], 1);
        int sl2 = atomicAdd(&g_cnt[d4.z], 1);
        int sl3 = atomicAdd(&g_cnt[d4.w], 1);
        if (sl0 < MAXDEG) g_csrp[d4.x * MAXDEG + sl0] = s4.x;
        if (sl1 < MAXDEG) g_csrp[d4.y * MAXDEG + sl1] = s4.y;
        if (sl2 < MAXDEG) g_csrp[d4.z * MAXDEG + sl2] = s4.z;
        if (sl3 < MAXDEG) g_csrp[d4.w * MAXDEG + sl3] = s4.w;
    } else if (q < FILL_T + XCVT_T) {
        int i = q - FILL_T;                  // 8-float chunk id
        float4 a = __ldg((const float4*)x + 2 * i);
        float4 b = __ldg((const float4*)x + 2 * i + 1);
        __half2 h0 = __floats2half2_rn(a.x, a.y);
        __half2 h1 = __floats2half2_rn(a.z, a.w);
        __half2 h2 = __floats2half2_rn(b.x, b.y);
        __half2 h3 = __floats2half2_rn(b.z, b.w);
        uint4 u;
        u.x = *(unsigned int*)&h0;
        u.y = *(unsigned int*)&h1;
        u.z = *(unsigned int*)&h2;
        u.w = *(unsigned int*)&h3;
        ((uint4*)g_xh)[i] = u;
    }
}

// ============================================================================
// Agg 1: 8 nodes per warp; 4 lanes x uint4 (8 fp16) cover the 32 channels.
// (identical to measured R15)
// ============================================================================
__global__ __launch_bounds__(256)
void k_agg1() {
    int gt   = blockIdx.x * blockDim.x + threadIdx.x;
    int wid  = gt >> 5;
    int lane = gt & 31;
    int sub  = lane >> 2;        // node within warp (0..7)
    int c4   = lane & 3;         // uint4 group (0..3)
    int n = wid * 8 + sub;
    if (n >= NN) return;

    int deg  = g_cnt[n];
    int degc = deg < MAXDEG ? deg : MAXDEG;
    const int*   row = &g_csrp[n * MAXDEG];
    const uint4* xp  = (const uint4*)g_xh;   // 4 uint4 per row

    unsigned long long ac[4];
#pragma unroll
    for (int i = 0; i < 4; i++) ac[i] = 0ull;

    int j = 0;
    for (; j + 7 < degc; j += 8) {
        int4 sA = __ldg((const int4*)(row + j));
        int4 sB = __ldg((const int4*)(row + j + 4));
        uint4 u0 = __ldg(xp + (sA.x * 4 + c4));
        uint4 u1 = __ldg(xp + (sA.y * 4 + c4));
        uint4 u2 = __ldg(xp + (sA.z * 4 + c4));
        uint4 u3 = __ldg(xp + (sA.w * 4 + c4));
        uint4 u4 = __ldg(xp + (sB.x * 4 + c4));
        uint4 u5 = __ldg(xp + (sB.y * 4 + c4));
        uint4 u6 = __ldg(xp + (sB.z * 4 + c4));
        uint4 u7 = __ldg(xp + (sB.w * 4 + c4));
#pragma unroll
        for (int q = 0; q < 8; q++) {
            uint4 u = (q == 0) ? u0 : (q == 1) ? u1 : (q == 2) ? u2 :
                      (q == 3) ? u3 : (q == 4) ? u4 : (q == 5) ? u5 :
                      (q == 6) ? u6 : u7;
            float2 f0 = __half22float2(*(__half2*)&u.x);
            float2 f1 = __half22float2(*(__half2*)&u.y);
            float2 f2 = __half22float2(*(__half2*)&u.z);
            float2 f3 = __half22float2(*(__half2*)&u.w);
            ADD2(ac[0], pack2(f0.x, f0.y));
            ADD2(ac[1], pack2(f1.x, f1.y));
            ADD2(ac[2], pack2(f2.x, f2.y));
            ADD2(ac[3], pack2(f3.x, f3.y));
        }
    }
    for (; j < degc; j++) {
        uint4 u = __ldg(xp + (__ldg(row + j) * 4 + c4));
        float2 f0 = __half22float2(*(__half2*)&u.x);
        float2 f1 = __half22float2(*(__half2*)&u.y);
        float2 f2 = __half22float2(*(__half2*)&u.z);
        float2 f3 = __half22float2(*(__half2*)&u.w);
        ADD2(ac[0], pack2(f0.x, f0.y));
        ADD2(ac[1], pack2(f1.x, f1.y));
        ADD2(ac[2], pack2(f2.x, f2.y));
        ADD2(ac[3], pack2(f3.x, f3.y));
    }
    float dinv = 1.0f / fmaxf((float)deg, 1.0f);
    float lo, hi;
    uint4 pkt;
    unpack2(lo, hi, ac[0]);
    __half2 h0 = __floats2half2_rn(lo * dinv, hi * dinv);
    pkt.x = *(unsigned int*)&h0;
    unpack2(lo, hi, ac[1]);
    __half2 h1 = __floats2half2_rn(lo * dinv, hi * dinv);
    pkt.y = *(unsigned int*)&h1;
    unpack2(lo, hi, ac[2]);
    __half2 h2 = __floats2half2_rn(lo * dinv, hi * dinv);
    pkt.z = *(unsigned int*)&h2;
    unpack2(lo, hi, ac[3]);
    __half2 h3 = __floats2half2_rn(lo * dinv, hi * dinv);
    pkt.w = *(unsigned int*)&h3;
    ((uint4*)g_agg1h)[n * 4 + c4] = pkt;
}

// ============================================================================
// Agg 2: 4 nodes per warp; 8 lanes x uint4 (8 fp16) cover the 64 channels.
// Indices as int4; main loop 8 neighbors deep; scalar FADD accumulation
// (the R14-measured 18.3us form). fp16 output. Restores g_cnt[n] = 0.
// ============================================================================
__global__ __launch_bounds__(256)
void k_agg2() {
    int gt   = blockIdx.x * blockDim.x + threadIdx.x;
    int wid  = gt >> 5;
    int lane = gt & 31;
    int sub  = lane >> 3;        // node within warp (0..3)
    int c8   = lane & 7;         // 8-halves group (0..7)
    int n = wid * 4 + sub;
    if (n >= NN) return;

    int deg  = g_cnt[n];
    int degc = deg < MAXDEG ? deg : MAXDEG;
    const int*   row = &g_csrp[n * MAXDEG];
    const uint4* hp  = (const uint4*)g_h;    // 8 halves per uint4

    float acc[8];
#pragma unroll
    for (int i = 0; i < 8; i++) acc[i] = 0.f;

    int j = 0;
    for (; j + 7 < degc; j += 8) {
        int4 sA = __ldg((const int4*)(row + j));
        int4 sB = __ldg((const int4*)(row + j + 4));
        uint4 u0 = __ldg(hp + (sA.x * 8 + c8));
        uint4 u1 = __ldg(hp + (sA.y * 8 + c8));
        uint4 u2 = __ldg(hp + (sA.z * 8 + c8));
        uint4 u3 = __ldg(hp + (sA.w * 8 + c8));
        uint4 u4 = __ldg(hp + (sB.x * 8 + c8));
        uint4 u5 = __ldg(hp + (sB.y * 8 + c8));
        uint4 u6 = __ldg(hp + (sB.z * 8 + c8));
        uint4 u7 = __ldg(hp + (sB.w * 8 + c8));
#pragma unroll
        for (int q = 0; q < 8; q++) {
            uint4 u = (q == 0) ? u0 : (q == 1) ? u1 : (q == 2) ? u2 :
                      (q == 3) ? u3 : (q == 4) ? u4 : (q == 5) ? u5 :
                      (q == 6) ? u6 : u7;
            float2 f0 = __half22float2(*(__half2*)&u.x);
            float2 f1 = __half22float2(*(__half2*)&u.y);
            float2 f2 = __half22float2(*(__half2*)&u.z);
            float2 f3 = __half22float2(*(__half2*)&u.w);
            acc[0] += f0.x; acc[1] += f0.y;
            acc[2] += f1.x; acc[3] += f1.y;
            acc[4] += f2.x; acc[5] += f2.y;
            acc[6] += f3.x; acc[7] += f3.y;
        }
    }
    for (; j + 3 < degc; j += 4) {
        int4 s = __ldg((const int4*)(row + j));
        uint4 u0 = __ldg(hp + (s.x * 8 + c8));
        uint4 u1 = __ldg(hp + (s.y * 8 + c8));
        uint4 u2 = __ldg(hp + (s.z * 8 + c8));
        uint4 u3 = __ldg(hp + (s.w * 8 + c8));
#pragma unroll
        for (int q = 0; q < 4; q++) {
            uint4 u = (q == 0) ? u0 : (q == 1) ? u1 : (q == 2) ? u2 : u3;
            float2 f0 = __half22float2(*(__half2*)&u.x);
            float2 f1 = __half22float2(*(__half2*)&u.y);
            float2 f2 = __half22float2(*(__half2*)&u.z);
            float2 f3 = __half22float2(*(__half2*)&u.w);
            acc[0] += f0.x; acc[1] += f0.y;
            acc[2] += f1.x; acc[3] += f1.y;
            acc[4] += f2.x; acc[5] += f2.y;
            acc[6] += f3.x; acc[7] += f3.y;
        }
    }
    for (; j < degc; j++) {
        uint4 u = __ldg(hp + (__ldg(row + j) * 8 + c8));
        float2 f0 = __half22float2(*(__half2*)&u.x);
        float2 f1 = __half22float2(*(__half2*)&u.y);
        float2 f2 = __half22float2(*(__half2*)&u.z);
        float2 f3 = __half22float2(*(__half2*)&u.w);
        acc[0] += f0.x; acc[1] += f0.y;
        acc[2] += f1.x; acc[3] += f1.y;
        acc[4] += f2.x; acc[5] += f2.y;
        acc[6] += f3.x; acc[7] += f3.y;
    }
    float dinv = 1.0f / fmaxf((float)deg, 1.0f);
    __half2 p0 = __floats2half2_rn(acc[0]*dinv, acc[1]*dinv);
    __half2 p1 = __floats2half2_rn(acc[2]*dinv, acc[3]*dinv);
    __half2 p2 = __floats2half2_rn(acc[4]*dinv, acc[5]*dinv);
    __half2 p3 = __floats2half2_rn(acc[6]*dinv, acc[7]*dinv);
    uint4 pkt;
    pkt.x = *(unsigned int*)&p0;
    pkt.y = *(unsigned int*)&p1;
    pkt.z = *(unsigned int*)&p2;
    pkt.w = *(unsigned int*)&p3;
    ((uint4*)g_agg2h)[n * 8 + c8] = pkt;
    if (c8 == 0) g_cnt[n] = 0;   // restore invariant
}

// ============================================================================
// Layer 1 via tensor cores: D[128x64] = [agg1h | xh] @ [W1l;W1r]
// (identical to measured R15)
// ============================================================================
#define L1_KH    72
#define L1_NH    72
#define L1_SA    0                            // 128*72*2 = 18432
#define L1_SB    18432                        // 64*72*2  = 9216
#define L1_ALPHA (18432 + 9216)               // 27648
#define L1_BETA  (L1_ALPHA + 256)
#define L1_SMEM  (L1_BETA + 256)              // 28160

__global__ __launch_bounds__(256)
void k_layer1(const float* __restrict__ W1l, const float* __restrict__ b1l,
              const float* __restrict__ W1r,
              const float* __restrict__ g1, const float* __restrict__ bb1,
              const float* __restrict__ m1, const float* __restrict__ v1) {
    extern __shared__ char smem_raw[];
    __half* SA = (__half*)(smem_raw + L1_SA);
    __half* SB = (__half*)(smem_raw + L1_SB);
    float* SAL = (float*)(smem_raw + L1_ALPHA);
    float* SBE = (float*)(smem_raw + L1_BETA);

    int t = threadIdx.x;
    int nb = blockIdx.x * 128;
    int lane = t & 31, w = t >> 5;

#pragma unroll
    for (int it = 0; it < 4; it++) {
        int f = t + 256 * it;            // uint4 id [0,1024): m = f>>3, g = f&7
        int m = f >> 3, g = f & 7;
        int n = nb + m; int nc = n < NN ? n : NN - 1;
        uint4 u = (g < 4) ? __ldg((const uint4*)g_agg1h + (nc * 4 + g))
                          : __ldg((const uint4*)g_xh + (nc * 4 + (g - 4)));
        *(uint4*)&SA[m * L1_KH + g * 8] = u;
    }
#pragma unroll
    for (int it = 0; it < 4; it++) {
        int f4 = t + 256 * it;           // float4 id [0,1024)
        int k = f4 >> 4, j = f4 & 15;
        float4 wv = (f4 < 512) ? __ldg((const float4*)W1l + f4)
                               : __ldg((const float4*)W1r + (f4 - 512));
        __half2 h01 = __floats2half2_rn(wv.x, wv.y);
        __half2 h23 = __floats2half2_rn(wv.z, wv.w);
        uint2 p;
        p.x = *(unsigned int*)&h01;
        p.y = *(unsigned int*)&h23;
        *(uint2*)&SB[k * L1_NH + j * 4] = p;
    }
    if (t < HIDC) {
        float a = g1[t] * rsqrtf(v1[t] + 1e-5f);
        SAL[t] = a;
        SBE[t] = (b1l[t] - m1[t]) * a + bb1[t];
    }
    __syncthreads();

    int m0 = w * 16;
    float d[8][4];
#pragma unroll
    for (int j = 0; j < 8; j++)
#pragma unroll
        for (int i = 0; i < 4; i++) d[j][i] = 0.f;

    int arow = m0 + (lane & 15);
    int akk  = (lane >> 4) * 8;
    int brow = lane & 15;

#pragma unroll
    for (int s = 0; s < 4; s++) {
        unsigned afr[4];
        unsigned aaddr = (unsigned)__cvta_generic_to_shared(
            &SA[arow * L1_KH + s * 16 + akk]);
        ldsm_x4(afr, aaddr);
#pragma unroll
        for (int j = 0; j < 8; j++) {
            unsigned b0, b1;
            unsigned baddr = (unsigned)__cvta_generic_to_shared(
                &SB[(s * 16 + brow) * L1_NH + j * 8]);
            ldsm_x2t(b0, b1, baddr);
            mma16816(d[j], afr, b0, b1);
        }
    }

    int r0 = lane >> 2;
    int cbase = 2 * (lane & 3);
    int n1 = nb + m0 + r0;
    int n2 = n1 + 8;
#pragma unroll
    for (int j = 0; j < 8; j++) {
        int c = 8 * j + cbase;
        float A0 = SAL[c],   B0 = SBE[c];
        float A1 = SAL[c+1], B1 = SBE[c+1];
        if (n1 < NN) {
            __half2 hv = __floats2half2_rn(
                fmaxf(d[j][0] * A0 + B0, 0.f),
                fmaxf(d[j][1] * A1 + B1, 0.f));
            *(__half2*)&g_h[(long long)n1 * HIDC + c] = hv;
        }
        if (n2 < NN) {
            __half2 hv = __floats2half2_rn(
                fmaxf(d[j][2] * A0 + B0, 0.f),
                fmaxf(d[j][3] * A1 + B1, 0.f));
            *(__half2*)&g_h[(long long)n2 * HIDC + c] = hv;
        }
    }
}

// ============================================================================
// Layer 2 + head via tensor cores (identical to measured R13/R14/R15)
// ============================================================================
#define L2_KH    136                          // SA row stride (halves)
#define L2_NH    72                           // SB row stride (halves)
#define L2_SA    0                            // 128*136*2 = 34816
#define L2_SB    34816                        // 128*72*2  = 18432
#define L2_ALPHA (34816 + 18432)              // 53248
#define L2_BETA  (L2_ALPHA + 256)
#define L2_SWO   (L2_BETA + 256)
#define L2_SMEM  (L2_SWO + 256)               // 54016

__global__ __launch_bounds__(256)
void k_layer2(const float* __restrict__ W2l, const float* __restrict__ b2l,
              const float* __restrict__ W2r,
              const float* __restrict__ g2, const float* __restrict__ bb2,
              const float* __restrict__ m2, const float* __restrict__ v2,
              const float* __restrict__ Wlin, const float* __restrict__ blin,
              float* __restrict__ out) {
    extern __shared__ char smem_raw[];
    __half* SA = (__half*)(smem_raw + L2_SA);
    __half* SB = (__half*)(smem_raw + L2_SB);
    float* SAL = (float*)(smem_raw + L2_ALPHA);
    float* SBE = (float*)(smem_raw + L2_BETA);
    float* SWO = (float*)(smem_raw + L2_SWO);

    int t = threadIdx.x;
    int nb = blockIdx.x * 128;
    int lane = t & 31, w = t >> 5;

#pragma unroll
    for (int it = 0; it < 8; it++) {
        int f = t + 256 * it;            // uint4 id [0,2048)
        int m = f >> 4, g = f & 15;
        int n = nb + m; int nc = n < NN ? n : NN - 1;
        uint4 u = (g < 8) ? __ldg((const uint4*)g_agg2h + (nc * 8 + g))
                          : __ldg((const uint4*)g_h + (nc * 8 + (g - 8)));
        *(uint4*)&SA[m * L2_KH + g * 8] = u;
    }
#pragma unroll
    for (int it = 0; it < 8; it++) {
        int f4 = t + 256 * it;           // float4 id [0,2048)
        int k = f4 >> 4, j = f4 & 15;
        float4 wv = (f4 < 1024) ? __ldg((const float4*)W2l + f4)
                                : __ldg((const float4*)W2r + (f4 - 1024));
        __half2 h01 = __floats2half2_rn(wv.x, wv.y);
        __half2 h23 = __floats2half2_rn(wv.z, wv.w);
        uint2 p;
        p.x = *(unsigned int*)&h01;
        p.y = *(unsigned int*)&h23;
        *(uint2*)&SB[k * L2_NH + j * 4] = p;
    }
    if (t < HIDC) {
        float a = g2[t] * rsqrtf(v2[t] + 1e-5f);
        SAL[t] = a;
        SBE[t] = (b2l[t] - m2[t]) * a + bb2[t];
        SWO[t] = Wlin[t];
    }
    __syncthreads();

    int m0 = w * 16;
    float d[8][4];
#pragma unroll
    for (int j = 0; j < 8; j++)
#pragma unroll
        for (int i = 0; i < 4; i++) d[j][i] = 0.f;

    int arow = m0 + (lane & 15);
    int akk  = (lane >> 4) * 8;
    int brow = lane & 15;

#pragma unroll
    for (int s = 0; s < 8; s++) {
        unsigned afr[4];
        unsigned aaddr = (unsigned)__cvta_generic_to_shared(
            &SA[arow * L2_KH + s * 16 + akk]);
        ldsm_x4(afr, aaddr);
#pragma unroll
        for (int j = 0; j < 8; j++) {
            unsigned b0, b1;
            unsigned baddr = (unsigned)__cvta_generic_to_shared(
                &SB[(s * 16 + brow) * L2_NH + j * 8]);
            ldsm_x2t(b0, b1, baddr);
            mma16816(d[j], afr, b0, b1);
        }
    }

    int r0 = lane >> 2;
    int cbase = 2 * (lane & 3);
    float p0 = 0.f, p1 = 0.f;
#pragma unroll
    for (int j = 0; j < 8; j++) {
        int c = 8 * j + cbase;
        float A0 = SAL[c],   B0 = SBE[c],   W0 = SWO[c];
        float A1 = SAL[c+1], B1 = SBE[c+1], W1 = SWO[c+1];
        p0 += fmaxf(d[j][0] * A0 + B0, 0.f) * W0
            + fmaxf(d[j][1] * A1 + B1, 0.f) * W1;
        p1 += fmaxf(d[j][2] * A0 + B0, 0.f) * W0
            + fmaxf(d[j][3] * A1 + B1, 0.f) * W1;
    }
    p0 += __shfl_xor_sync(0xFFFFFFFFu, p0, 1);
    p0 += __shfl_xor_sync(0xFFFFFFFFu, p0, 2);
    p1 += __shfl_xor_sync(0xFFFFFFFFu, p1, 1);
    p1 += __shfl_xor_sync(0xFFFFFFFFu, p1, 2);
    if ((lane & 3) == 0) {
        float bb = __ldg(&blin[0]);
        int n1 = nb + m0 + r0;
        int n2 = n1 + 8;
        if (n1 < NN) out[n1] = p0 + bb;
        if (n2 < NN) out[n2] = p1 + bb;
    }
}

// ============================================================================
// Launch — 5 kernels
// ============================================================================
extern "C" void kernel_launch(void* const* d_in, const int* in_sizes, int n_in,
                              void* d_out, int out_size) {
    const float* x   = (const float*)d_in[0];
    const int*   ei  = (const int*)d_in[1];   // int32 (jax x64 disabled)
    const int*   src = ei;
    const int*   dst = ei + EE;
    const float* W1l  = (const float*)d_in[2];
    const float* b1l  = (const float*)d_in[3];
    const float* W1r  = (const float*)d_in[4];
    const float* bn1g = (const float*)d_in[5];
    const float* bn1b = (const float*)d_in[6];
    const float* bn1m = (const float*)d_in[7];
    const float* bn1v = (const float*)d_in[8];
    const float* W2l  = (const float*)d_in[9];
    const float* b2l  = (const float*)d_in[10];
    const float* W2r  = (const float*)d_in[11];
    const float* bn2g = (const float*)d_in[12];
    const float* bn2b = (const float*)d_in[13];
    const float* bn2m = (const float*)d_in[14];
    const float* bn2v = (const float*)d_in[15];
    const float* Wlin = (const float*)d_in[16];
    const float* blin = (const float*)d_in[17];
    float* out = (float*)d_out;

    cudaFuncSetAttribute(k_layer1, cudaFuncAttributeMaxDynamicSharedMemorySize, L1_SMEM);
    cudaFuncSetAttribute(k_layer2, cudaFuncAttributeMaxDynamicSharedMemorySize, L2_SMEM);

    int nblk  = (NN + 127) / 128;              // 391
    int fblk  = (FILL_T + XCVT_T + 255) / 256; // 1563
    int a1blk = (NN * 4 + 255) / 256;          // 782   (8 nodes/warp)
    int a2blk = (NN * 8 + 255) / 256;          // 1563  (4 nodes/warp)

    k_fill<<<fblk, 256>>>(src, dst, x);
    k_agg1<<<a1blk, 256>>>();
    k_layer1<<<nblk, 256, L1_SMEM>>>(W1l, b1l, W1r, bn1g, bn1b, bn1m, bn1v);
    k_agg2<<<a2blk, 256>>>();
    k_layer2<<<nblk, 256, L2_SMEM>>>(W2l, b2l, W2r, bn2g, bn2b, bn2m, bn2v,
                                     Wlin, blin, out);
}